// round 15
// baseline (speedup 1.0000x reference)
#include <cuda_runtime.h>
#include <cuda_fp16.h>
#include <math.h>
#include <stdint.h>

#define DIM   1024
#define NH    16
#define HD    64
#define BATCH 4
#define NSEQ  2048
#define MSEQ  2048

typedef uint16_t U16;

// ---------------- device scratch (no runtime allocation) ----------------
__device__ U16 s_tgt16[8388608];
__device__ U16 s_src16[8388608];
__device__ U16 s_x16  [8388608];
__device__ U16 s_wq16 [1048576];
__device__ U16 s_wkv16[2097152];
__device__ U16 s_wo16 [1048576];
__device__ U16 s_q16 [8388608];
__device__ U16 s_k16 [8388608];
__device__ U16 s_v16 [8388608];

// ---------------- fp16 helpers ----------------
__device__ __forceinline__ uint32_t hpack(float e0, float e1) {
    __half2 h = __floats2half2_rn(e0, e1);
    return *(uint32_t*)&h;
}
__device__ __forceinline__ void mma_f16(float* c, const uint32_t* a, const uint32_t* b) {
    asm volatile("mma.sync.aligned.m16n8k16.row.col.f32.f16.f16.f32 "
                 "{%0,%1,%2,%3}, {%4,%5,%6,%7}, {%8,%9}, {%0,%1,%2,%3};"
                 : "+f"(c[0]), "+f"(c[1]), "+f"(c[2]), "+f"(c[3])
                 : "r"(a[0]), "r"(a[1]), "r"(a[2]), "r"(a[3]), "r"(b[0]), "r"(b[1]));
}
__device__ __forceinline__ void ldsm4(uint32_t& r0, uint32_t& r1, uint32_t& r2, uint32_t& r3,
                                      uint32_t a) {
    asm volatile("ldmatrix.sync.aligned.m8n8.x4.shared.b16 {%0,%1,%2,%3}, [%4];"
                 : "=r"(r0), "=r"(r1), "=r"(r2), "=r"(r3) : "r"(a));
}
__device__ __forceinline__ void ldsm4t(uint32_t& r0, uint32_t& r1, uint32_t& r2, uint32_t& r3,
                                       uint32_t a) {
    asm volatile("ldmatrix.sync.aligned.m8n8.x4.trans.shared.b16 {%0,%1,%2,%3}, [%4];"
                 : "=r"(r0), "=r"(r1), "=r"(r2), "=r"(r3) : "r"(a));
}
__device__ __forceinline__ void cpa16(uint32_t dst, const void* src) {
    asm volatile("cp.async.cg.shared.global [%0], [%1], 16;" :: "r"(dst), "l"(src));
}
#define CPA_COMMIT asm volatile("cp.async.commit_group;")
#define CPA_WAIT2  asm volatile("cp.async.wait_group 2;")
#define CPA_WAIT1  asm volatile("cp.async.wait_group 1;")
#define CPA_WAIT0  asm volatile("cp.async.wait_group 0;")

// byte offset in a [rows][64 fp16] tile, 128B rows, SW128 swizzle
__device__ __forceinline__ uint32_t sw128(int row, int ch) {
    return (uint32_t)(row * 128 + ((ch ^ (row & 7)) << 4));
}

// inv_freq table (compile-time, fp64-exact)
constexpr double pw32(int e) {
    double p = 1.0, b = 1.3335214321633240879;   // 10000^(1/32)
    for (int i = 0; i < 5; i++) { if (e & 1) p *= b; b *= b; e >>= 1; }
    return p;
}
#define IFV(i) ((float)(1.0 / pw32(i)))
__constant__ float INVF[32] = {
    IFV(0),  IFV(1),  IFV(2),  IFV(3),  IFV(4),  IFV(5),  IFV(6),  IFV(7),
    IFV(8),  IFV(9),  IFV(10), IFV(11), IFV(12), IFV(13), IFV(14), IFV(15),
    IFV(16), IFV(17), IFV(18), IFV(19), IFV(20), IFV(21), IFV(22), IFV(23),
    IFV(24), IFV(25), IFV(26), IFV(27), IFV(28), IFV(29), IFV(30), IFV(31)
};

// ---------------------------------------------------------------------------
// merged conversion kernel (round-14, unchanged)
// ---------------------------------------------------------------------------
__global__ __launch_bounds__(256) void megaconv_kernel(
    const float* __restrict__ tgt, const float* __restrict__ src,
    const float* __restrict__ Wq, const float* __restrict__ Wkv,
    const float* __restrict__ Wo,
    U16* __restrict__ tgt16, U16* __restrict__ src16,
    U16* __restrict__ wq16, U16* __restrict__ wkv16, U16* __restrict__ wo16)
{
    __shared__ float ts[32][33];
    const int blk = blockIdx.x, tid = threadIdx.x;

    if (blk < 16384) {
        const float* in = (blk < 8192) ? tgt : src;
        U16* out = (blk < 8192) ? tgt16 : src16;
        const int i = (blk & 8191) * 256 + tid;
        float4 v = ((const float4*)in)[i];
        ((uint2*)out)[i] = make_uint2(hpack(v.x, v.y), hpack(v.z, v.w));
        return;
    }

    const float* B; U16* o; int N, id;
    if (blk < 17408)      { B = Wq;  o = wq16;  N = 1024; id = blk - 16384; }
    else if (blk < 19456) { B = Wkv; o = wkv16; N = 2048; id = blk - 17408; }
    else                  { B = Wo;  o = wo16;  N = 1024; id = blk - 19456; }
    const int K = 1024;
    const int xb = N >> 5;
    const int n0 = (id % xb) * 32, k0 = (id / xb) * 32;
    const int tx = tid & 31, ty = tid >> 5;

    #pragma unroll
    for (int i = 0; i < 4; i++)
        ts[ty + 8 * i][tx] = B[(size_t)(k0 + ty + 8 * i) * N + n0 + tx];
    __syncthreads();
    #pragma unroll
    for (int i = 0; i < 4; i++) {
        const int r = ty + 8 * i;
        __half hv = __float2half_rn(ts[tx][r]);
        o[(size_t)(n0 + r) * K + k0 + tx] = *(U16*)&hv;
    }
}

// ---------------------------------------------------------------------------
// shared GEMM core: 3-stage cp.async pipeline, ONE barrier per chunk,
// refill issued before compute. Math identical to round 14.
// ---------------------------------------------------------------------------
#define TG_STAGE 32768
#define GEMM_SMEM (3 * TG_STAGE)   // 98304

__device__ __forceinline__ void gemm_core(
    int mode, const U16* __restrict__ A16, const U16* __restrict__ B16,
    float* __restrict__ C, const int* __restrict__ pos, const float* __restrict__ nw,
    U16* __restrict__ o1, U16* __restrict__ o2,
    int N, int K, int brow, int bcol, U16* smg)
{
    const uint32_t smb = (uint32_t)__cvta_generic_to_shared(smg);
    const int tid = threadIdx.x, warp = tid >> 5, lane = tid & 31;
    const int wm = (warp >> 1) * 32, wn = (warp & 1) * 64;
    const int fr = ((lane >> 3) & 1) * 8 + (lane & 7);
    const int fc = lane >> 4;

    float acc[2][8][4];
    #pragma unroll
    for (int a = 0; a < 2; a++)
        #pragma unroll
        for (int b = 0; b < 8; b++)
            #pragma unroll
            for (int c = 0; c < 4; c++) acc[a][b][c] = 0.0f;

    auto stage = [&](int ck, int s) {
        const uint32_t base = smb + s * TG_STAGE;
        const int k0 = ck << 6;
        #pragma unroll
        for (int i = 0; i < 4; i++) {
            const int id = tid + i * 256;
            const int r = id >> 3, ch = id & 7;
            const uint32_t so = sw128(r, ch);
            cpa16(base + so,         A16 + (size_t)(brow + r) * K + k0 + ch * 8);
            cpa16(base + 16384 + so, B16 + (size_t)(bcol + r) * K + k0 + ch * 8);
        }
    };

    stage(0, 0); CPA_COMMIT;
    stage(1, 1); CPA_COMMIT;

    const int nCk = K >> 6;
    for (int ck = 0; ck < nCk; ck++) {
        if (ck == nCk - 1) { CPA_WAIT0; } else { CPA_WAIT1; }
        __syncthreads();
        // refill buffer (ck+2)%3 — last read at iteration ck-1, covered by the sync
        if (ck + 2 < nCk) { stage(ck + 2, (ck + 2) % 3); CPA_COMMIT; }

        const uint32_t tb = smb + (ck % 3) * TG_STAGE;

        #pragma unroll
        for (int kc = 0; kc < 4; kc++) {
            uint32_t af[2][4];
            #pragma unroll
            for (int mi = 0; mi < 2; mi++) {
                const uint32_t a = tb + sw128(wm + mi * 16 + fr, kc * 2 + fc);
                ldsm4(af[mi][0], af[mi][1], af[mi][2], af[mi][3], a);
            }
            #pragma unroll
            for (int ng = 0; ng < 4; ng++) {
                uint32_t bh4[4];
                const uint32_t ba = tb + 16384 + sw128(wn + ng * 16 + fr, kc * 2 + fc);
                ldsm4(bh4[0], bh4[1], bh4[2], bh4[3], ba);
                #pragma unroll
                for (int mi = 0; mi < 2; mi++)
                    #pragma unroll
                    for (int oo = 0; oo < 2; oo++) {
                        uint32_t bhf[2] = { bh4[oo], bh4[oo + 2] };
                        mma_f16(acc[mi][ng * 2 + oo], af[mi], bhf);
                    }
            }
        }
    }

    // ---------------- epilogue (unchanged) ----------------
    if (mode == 0) {
        #pragma unroll
        for (int mi = 0; mi < 2; mi++)
            #pragma unroll
            for (int nj = 0; nj < 8; nj++) {
                const float* c = acc[mi][nj];
                const int row = brow + wm + mi * 16 + (lane >> 2);
                const int col = bcol + wn + (nj >> 1) * 16 + (nj & 1) * 8 + (lane & 3) * 2;
                *(float2*)(C + (size_t)row * N + col)       = make_float2(c[0], c[1]);
                *(float2*)(C + (size_t)(row + 8) * N + col) = make_float2(c[2], c[3]);
            }
        return;
    }

    const int q = lane & 3, g = lane >> 2;
    const int headbase = bcol + wn;
    const bool vpath = (mode == 2) && (headbase >= 1024);

    #pragma unroll
    for (int mi = 0; mi < 2; mi++) {
        #pragma unroll
        for (int half = 0; half < 2; half++) {
            const int row = brow + wm + mi * 16 + g + half * 8;

            if (vpath) {
                const size_t ob = (size_t)row * 1024 + (headbase - 1024);
                #pragma unroll
                for (int nj = 0; nj < 8; nj++) {
                    const int cn = (nj >> 1) * 16 + (nj & 1) * 8 + q * 2;
                    *(uint32_t*)(o2 + ob + cn) =
                        hpack(acc[mi][nj][half * 2], acc[mi][nj][half * 2 + 1]);
                }
                continue;
            }

            float ss = 0.0f;
            #pragma unroll
            for (int nj = 0; nj < 8; nj++) {
                const float a0 = acc[mi][nj][half * 2];
                const float a1 = acc[mi][nj][half * 2 + 1];
                ss += a0 * a0 + a1 * a1;
            }
            ss += __shfl_xor_sync(0xffffffffu, ss, 1);
            ss += __shfl_xor_sync(0xffffffffu, ss, 2);
            const float inv = rsqrtf(ss * (1.0f / 64.0f) + 1.1920929e-07f);
            const float fpos = (float)pos[row];
            const float scale = (mode == 1) ? 0.125f : 1.0f;
            const size_t ob = (size_t)row * 1024 + headbase;

            #pragma unroll
            for (int p = 0; p < 4; p++) {
                const int c0 = (p >> 1) * 16 + (p & 1) * 8 + q * 2;
                float oA[2], oB[2];
                #pragma unroll
                for (int e = 0; e < 2; e++) {
                    const int c = c0 + e;
                    const float y1 = acc[mi][p][half * 2 + e]     * inv * nw[c]      * scale;
                    const float y2 = acc[mi][p + 4][half * 2 + e] * inv * nw[c + 32] * scale;
                    float sn, cs;
                    sincosf(fpos * INVF[c], &sn, &cs);
                    oA[e] = y1 * cs - y2 * sn;
                    oB[e] = y2 * cs + y1 * sn;
                }
                *(uint32_t*)(o1 + ob + c0)      = hpack(oA[0], oA[1]);
                *(uint32_t*)(o1 + ob + c0 + 32) = hpack(oB[0], oB[1]);
            }
        }
    }
}

// combined Q + KV projection launch: grid (24, 64).
__global__ __launch_bounds__(256, 2) void qkv_kernel(
    const U16* __restrict__ tgt16, const U16* __restrict__ src16,
    const U16* __restrict__ wq16, const U16* __restrict__ wkv16,
    const int* __restrict__ tgt_pos, const int* __restrict__ src_pos,
    const float* __restrict__ qw, const float* __restrict__ kw,
    U16* __restrict__ q16, U16* __restrict__ k16, U16* __restrict__ v16)
{
    extern __shared__ U16 smg[];
    const int bx = blockIdx.x, brow = blockIdx.y * 128;
    if (bx < 8)
        gemm_core(1, tgt16, wq16, nullptr, tgt_pos, qw, q16, nullptr,
                  1024, 1024, brow, bx * 128, smg);
    else
        gemm_core(2, src16, wkv16, nullptr, src_pos, kw, k16, v16,
                  2048, 1024, brow, (bx - 8) * 128, smg);
}

__global__ __launch_bounds__(256, 2) void gemm_o_kernel(
    const U16* __restrict__ A16, const U16* __restrict__ B16, float* __restrict__ C)
{
    extern __shared__ U16 smg[];
    gemm_core(0, A16, B16, C, nullptr, nullptr, nullptr, nullptr,
              1024, 1024, blockIdx.y * 128, blockIdx.x * 128, smg);
}

// ---------------------------------------------------------------------------
// fp16 flash attention, fixed-max softmax, 3-stage KV pipeline, one barrier
// per kv-tile, refill before compute.
// smem: Q 16K @0 | KV stages s=0..2 @ 16384 + s*16384   (total 64KB)
// ---------------------------------------------------------------------------
#define ATT_SMEM 65536

__global__ __launch_bounds__(256, 2) void attn_f16(
    const U16* __restrict__ q16_, const U16* __restrict__ k16_,
    const U16* __restrict__ v16_, U16* __restrict__ x16_)
{
    extern __shared__ U16 sma[];
    const uint32_t smb = (uint32_t)__cvta_generic_to_shared(sma);
    const int tid = threadIdx.x, warp = tid >> 5, lane = tid & 31;
    const int b = blockIdx.y >> 4, h = blockIdx.y & 15;
    const int row0 = blockIdx.x * 128;
    const int wm = warp * 16;
    const int fr = ((lane >> 3) & 1) * 8 + (lane & 7);
    const int fc = lane >> 4;

    const size_t bn0 = (size_t)b * NSEQ + row0;
    const size_t bm0 = (size_t)b * MSEQ;

    // ---- stage Q (group 0) ----
    #pragma unroll
    for (int i = 0; i < 4; i++) {
        const int c = tid + i * 256;
        const int r = c >> 3, ch = c & 7;
        const size_t g = (bn0 + r) * 1024 + h * HD + ch * 8;
        cpa16(smb + sw128(r, ch), q16_ + g);
    }
    CPA_COMMIT;

    auto stageKV = [&](int kt, int s) {
        const uint32_t base = smb + 16384 + s * 16384;
        #pragma unroll
        for (int i = 0; i < 2; i++) {
            const int c = tid + i * 256;
            const int r = c >> 3, ch = c & 7;
            const size_t g = (bm0 + kt * 64 + r) * 1024 + h * HD + ch * 8;
            const uint32_t so = sw128(r, ch);
            cpa16(base + so,        k16_ + g);
            cpa16(base + 8192 + so, v16_ + g);
        }
    };
    stageKV(0, 0); CPA_COMMIT;   // group 1
    stageKV(1, 1); CPA_COMMIT;   // group 2

    // ---- pull Q fragments into registers (once) ----
    CPA_WAIT2;        // group 0 (Q) complete
    __syncthreads();
    uint32_t qf[4][4];
    #pragma unroll
    for (int kc = 0; kc < 4; kc++)
        ldsm4(qf[kc][0], qf[kc][1], qf[kc][2], qf[kc][3],
              smb + sw128(wm + fr, kc * 2 + fc));

    float li0 = 0.0f, li1 = 0.0f;
    float acc[8][4];
    #pragma unroll
    for (int na = 0; na < 8; na++)
        #pragma unroll
        for (int c = 0; c < 4; c++) acc[na][c] = 0.0f;

    const int nT = MSEQ / 64;
    for (int kt = 0; kt < nT; kt++) {
        if (kt == nT - 1) { CPA_WAIT0; } else { CPA_WAIT1; }
        __syncthreads();
        // refill buffer (kt+2)%3 — last read at kt-1, covered by the sync
        if (kt + 2 < nT) { stageKV(kt + 2, (kt + 2) % 3); CPA_COMMIT; }

        const uint32_t kb = smb + 16384 + (kt % 3) * 16384;

        // ---- S = Q K^T ----
        float s[8][4];
        #pragma unroll
        for (int na = 0; na < 8; na++)
            #pragma unroll
            for (int c = 0; c < 4; c++) s[na][c] = 0.0f;

        #pragma unroll
        for (int kc = 0; kc < 4; kc++) {
            #pragma unroll
            for (int jg = 0; jg < 4; jg++) {
                uint32_t kr[4];
                ldsm4(kr[0], kr[1], kr[2], kr[3],
                      kb + sw128(jg * 16 + fr, kc * 2 + fc));
                #pragma unroll
                for (int oo = 0; oo < 2; oo++) {
                    uint32_t bh[2] = { kr[oo], kr[oo + 2] };
                    mma_f16(s[jg * 2 + oo], qf[kc], bh);
                }
            }
        }

        // ---- fixed-max softmax: p = exp(s - 8) ----
        #pragma unroll
        for (int na = 0; na < 8; na++) {
            s[na][0] = __expf(s[na][0] - 8.0f);
            s[na][1] = __expf(s[na][1] - 8.0f);
            s[na][2] = __expf(s[na][2] - 8.0f);
            s[na][3] = __expf(s[na][3] - 8.0f);
            li0 += s[na][0] + s[na][1];
            li1 += s[na][2] + s[na][3];
        }

        // ---- O += P V ----
        #pragma unroll
        for (int jc = 0; jc < 4; jc++) {
            uint32_t ph[4];
            ph[0] = hpack(s[2 * jc][0],     s[2 * jc][1]);
            ph[1] = hpack(s[2 * jc][2],     s[2 * jc][3]);
            ph[2] = hpack(s[2 * jc + 1][0], s[2 * jc + 1][1]);
            ph[3] = hpack(s[2 * jc + 1][2], s[2 * jc + 1][3]);
            #pragma unroll
            for (int dg = 0; dg < 4; dg++) {
                uint32_t vr[4];
                ldsm4t(vr[0], vr[1], vr[2], vr[3],
                       kb + 8192 + sw128(jc * 16 + fr, dg * 2 + fc));
                #pragma unroll
                for (int oo = 0; oo < 2; oo++) {
                    uint32_t bh[2] = { vr[oo * 2], vr[oo * 2 + 1] };
                    mma_f16(acc[dg * 2 + oo], ph, bh);
                }
            }
        }
    }

    li0 += __shfl_xor_sync(0xffffffffu, li0, 1);
    li0 += __shfl_xor_sync(0xffffffffu, li0, 2);
    li1 += __shfl_xor_sync(0xffffffffu, li1, 1);
    li1 += __shfl_xor_sync(0xffffffffu, li1, 2);
    const float inv0 = 1.0f / li0;
    const float inv1 = 1.0f / li1;
    const size_t r0 = bn0 + wm + (lane >> 2);
    const size_t e0 = r0 * 1024 + h * HD + (lane & 3) * 2;
    const size_t e1 = (r0 + 8) * 1024 + h * HD + (lane & 3) * 2;
    #pragma unroll
    for (int na = 0; na < 8; na++) {
        *(uint32_t*)(x16_ + e0 + na * 8) = hpack(acc[na][0] * inv0, acc[na][1] * inv0);
        *(uint32_t*)(x16_ + e1 + na * 8) = hpack(acc[na][2] * inv1, acc[na][3] * inv1);
    }
}

// ---------------------------------------------------------------------------
extern "C" void kernel_launch(void* const* d_in, const int* in_sizes, int n_in,
                              void* d_out, int out_size)
{
    const float* tgt     = (const float*)d_in[0];
    const float* src     = (const float*)d_in[1];
    const int*   tgt_pos = (const int*)  d_in[2];
    const int*   src_pos = (const int*)  d_in[3];
    const float* Wq      = (const float*)d_in[4];
    const float* Wkv     = (const float*)d_in[5];
    const float* Wo      = (const float*)d_in[6];
    const float* qw      = (const float*)d_in[7];
    const float* kw      = (const float*)d_in[8];
    float* out = (float*)d_out;

    U16 *tgt16, *src16, *x16, *wq16, *wkv16, *wo16;
    U16 *q16, *k16, *v16;
    cudaGetSymbolAddress((void**)&tgt16, s_tgt16);
    cudaGetSymbolAddress((void**)&src16, s_src16);
    cudaGetSymbolAddress((void**)&x16,   s_x16);
    cudaGetSymbolAddress((void**)&wq16,  s_wq16);
    cudaGetSymbolAddress((void**)&wkv16, s_wkv16);
    cudaGetSymbolAddress((void**)&wo16,  s_wo16);
    cudaGetSymbolAddress((void**)&q16,   s_q16);
    cudaGetSymbolAddress((void**)&k16,   s_k16);
    cudaGetSymbolAddress((void**)&v16,   s_v16);

    cudaFuncSetAttribute(qkv_kernel,
                         cudaFuncAttributeMaxDynamicSharedMemorySize, GEMM_SMEM);
    cudaFuncSetAttribute(gemm_o_kernel,
                         cudaFuncAttributeMaxDynamicSharedMemorySize, GEMM_SMEM);
    cudaFuncSetAttribute(attn_f16,
                         cudaFuncAttributeMaxDynamicSharedMemorySize, ATT_SMEM);

    // --- all conversions in one launch ---
    megaconv_kernel<<<20480, 256>>>(tgt, src, Wq, Wkv, Wo,
                                    tgt16, src16, wq16, wkv16, wo16);

    // --- Q + KV projections (merged launch) with fused epilogues ---
    qkv_kernel<<<dim3(24, 64), 256, GEMM_SMEM>>>(
        tgt16, src16, wq16, wkv16, tgt_pos, src_pos, qw, kw, q16, k16, v16);

    // --- attention ---
    attn_f16<<<dim3(16, 64), 256, ATT_SMEM>>>(q16, k16, v16, x16);

    // --- output projection (fp32 out) ---
    gemm_o_kernel<<<dim3(8, 64), 256, GEMM_SMEM>>>(x16, wo16, out);
}

// round 16
// speedup vs baseline: 1.0832x; 1.0832x over previous
#include <cuda_runtime.h>
#include <cuda_fp16.h>
#include <math.h>
#include <stdint.h>

#define DIM   1024
#define NH    16
#define HD    64
#define BATCH 4
#define NSEQ  2048
#define MSEQ  2048

typedef uint16_t U16;

// ---------------- device scratch (no runtime allocation) ----------------
__device__ U16 s_tgt16[8388608];
__device__ U16 s_src16[8388608];
__device__ U16 s_x16  [8388608];
__device__ U16 s_wq16 [1048576];
__device__ U16 s_wkv16[2097152];
__device__ U16 s_wo16 [1048576];
__device__ U16 s_q16 [8388608];
__device__ U16 s_k16 [8388608];
__device__ U16 s_v16 [8388608];

// dependency counters (zeroed by megaconv each replay)
__device__ int g_qcnt[64];    // Q row-blocks ready (target 8)
__device__ int g_kvcnt[4];    // KV blocks per batch (target 256)
__device__ int g_xcnt[64];    // x row-blocks ready (target 16)

// ---------------- fp16 helpers ----------------
__device__ __forceinline__ uint32_t hpack(float e0, float e1) {
    __half2 h = __floats2half2_rn(e0, e1);
    return *(uint32_t*)&h;
}
__device__ __forceinline__ void mma_f16(float* c, const uint32_t* a, const uint32_t* b) {
    asm volatile("mma.sync.aligned.m16n8k16.row.col.f32.f16.f16.f32 "
                 "{%0,%1,%2,%3}, {%4,%5,%6,%7}, {%8,%9}, {%0,%1,%2,%3};"
                 : "+f"(c[0]), "+f"(c[1]), "+f"(c[2]), "+f"(c[3])
                 : "r"(a[0]), "r"(a[1]), "r"(a[2]), "r"(a[3]), "r"(b[0]), "r"(b[1]));
}
__device__ __forceinline__ void ldsm4(uint32_t& r0, uint32_t& r1, uint32_t& r2, uint32_t& r3,
                                      uint32_t a) {
    asm volatile("ldmatrix.sync.aligned.m8n8.x4.shared.b16 {%0,%1,%2,%3}, [%4];"
                 : "=r"(r0), "=r"(r1), "=r"(r2), "=r"(r3) : "r"(a));
}
__device__ __forceinline__ void ldsm4t(uint32_t& r0, uint32_t& r1, uint32_t& r2, uint32_t& r3,
                                       uint32_t a) {
    asm volatile("ldmatrix.sync.aligned.m8n8.x4.trans.shared.b16 {%0,%1,%2,%3}, [%4];"
                 : "=r"(r0), "=r"(r1), "=r"(r2), "=r"(r3) : "r"(a));
}
__device__ __forceinline__ void cpa16(uint32_t dst, const void* src) {
    asm volatile("cp.async.cg.shared.global [%0], [%1], 16;" :: "r"(dst), "l"(src));
}
#define CPA_COMMIT asm volatile("cp.async.commit_group;")
#define CPA_WAIT2  asm volatile("cp.async.wait_group 2;")
#define CPA_WAIT1  asm volatile("cp.async.wait_group 1;")
#define CPA_WAIT0  asm volatile("cp.async.wait_group 0;")

__device__ __forceinline__ uint32_t sw128(int row, int ch) {
    return (uint32_t)(row * 128 + ((ch ^ (row & 7)) << 4));
}

// producer signal: all stores visible, then bump counter
__device__ __forceinline__ void signal_cnt(int* cnt) {
    __threadfence();
    __syncthreads();
    if (threadIdx.x == 0) atomicAdd(cnt, 1);
}
// consumer wait
__device__ __forceinline__ void wait_cnt(const int* cnt, int target) {
    if (threadIdx.x == 0) {
        const volatile int* p = cnt;
        while (*p < target) __nanosleep(128);
        __threadfence();
    }
    __syncthreads();
}

// inv_freq table (compile-time, fp64-exact)
constexpr double pw32(int e) {
    double p = 1.0, b = 1.3335214321633240879;   // 10000^(1/32)
    for (int i = 0; i < 5; i++) { if (e & 1) p *= b; b *= b; e >>= 1; }
    return p;
}
#define IFV(i) ((float)(1.0 / pw32(i)))
__constant__ float INVF[32] = {
    IFV(0),  IFV(1),  IFV(2),  IFV(3),  IFV(4),  IFV(5),  IFV(6),  IFV(7),
    IFV(8),  IFV(9),  IFV(10), IFV(11), IFV(12), IFV(13), IFV(14), IFV(15),
    IFV(16), IFV(17), IFV(18), IFV(19), IFV(20), IFV(21), IFV(22), IFV(23),
    IFV(24), IFV(25), IFV(26), IFV(27), IFV(28), IFV(29), IFV(30), IFV(31)
};

// ---------------------------------------------------------------------------
// merged conversion kernel + counter zeroing
// ---------------------------------------------------------------------------
__global__ __launch_bounds__(256) void megaconv_kernel(
    const float* __restrict__ tgt, const float* __restrict__ src,
    const float* __restrict__ Wq, const float* __restrict__ Wkv,
    const float* __restrict__ Wo,
    U16* __restrict__ tgt16, U16* __restrict__ src16,
    U16* __restrict__ wq16, U16* __restrict__ wkv16, U16* __restrict__ wo16)
{
    __shared__ float ts[32][33];
    const int blk = blockIdx.x, tid = threadIdx.x;

    if (blk == 0 && tid < 64) {
        g_qcnt[tid] = 0;
        g_xcnt[tid] = 0;
        if (tid < 4) g_kvcnt[tid] = 0;
    }

    if (blk < 16384) {
        const float* in = (blk < 8192) ? tgt : src;
        U16* out = (blk < 8192) ? tgt16 : src16;
        const int i = (blk & 8191) * 256 + tid;
        float4 v = ((const float4*)in)[i];
        ((uint2*)out)[i] = make_uint2(hpack(v.x, v.y), hpack(v.z, v.w));
        return;
    }

    const float* B; U16* o; int N, id;
    if (blk < 17408)      { B = Wq;  o = wq16;  N = 1024; id = blk - 16384; }
    else if (blk < 19456) { B = Wkv; o = wkv16; N = 2048; id = blk - 17408; }
    else                  { B = Wo;  o = wo16;  N = 1024; id = blk - 19456; }
    const int K = 1024;
    const int xb = N >> 5;
    const int n0 = (id % xb) * 32, k0 = (id / xb) * 32;
    const int tx = tid & 31, ty = tid >> 5;

    #pragma unroll
    for (int i = 0; i < 4; i++)
        ts[ty + 8 * i][tx] = B[(size_t)(k0 + ty + 8 * i) * N + n0 + tx];
    __syncthreads();
    #pragma unroll
    for (int i = 0; i < 4; i++) {
        const int r = ty + 8 * i;
        __half hv = __float2half_rn(ts[tx][r]);
        o[(size_t)(n0 + r) * K + k0 + tx] = *(U16*)&hv;
    }
}

// ---------------------------------------------------------------------------
// GEMM core — round-14 two-stage version (math unchanged).
// ---------------------------------------------------------------------------
#define TG_STAGE 32768
#define FUSED_SMEM 65536

__device__ __forceinline__ void gemm_core(
    int mode, const U16* __restrict__ A16, const U16* __restrict__ B16,
    float* __restrict__ C, const int* __restrict__ pos, const float* __restrict__ nw,
    U16* __restrict__ o1, U16* __restrict__ o2,
    int N, int K, int brow, int bcol, U16* smg)
{
    const uint32_t smb = (uint32_t)__cvta_generic_to_shared(smg);
    const int tid = threadIdx.x, warp = tid >> 5, lane = tid & 31;
    const int wm = (warp >> 1) * 32, wn = (warp & 1) * 64;
    const int fr = ((lane >> 3) & 1) * 8 + (lane & 7);
    const int fc = lane >> 4;

    float acc[2][8][4];
    #pragma unroll
    for (int a = 0; a < 2; a++)
        #pragma unroll
        for (int b = 0; b < 8; b++)
            #pragma unroll
            for (int c = 0; c < 4; c++) acc[a][b][c] = 0.0f;

    auto stage = [&](int ck, int s) {
        const uint32_t base = smb + s * TG_STAGE;
        const int k0 = ck << 6;
        #pragma unroll
        for (int i = 0; i < 4; i++) {
            const int id = tid + i * 256;
            const int r = id >> 3, ch = id & 7;
            const uint32_t so = sw128(r, ch);
            cpa16(base + so,         A16 + (size_t)(brow + r) * K + k0 + ch * 8);
            cpa16(base + 16384 + so, B16 + (size_t)(bcol + r) * K + k0 + ch * 8);
        }
    };

    stage(0, 0); CPA_COMMIT;
    stage(1, 1); CPA_COMMIT;

    const int nCk = K >> 6;
    for (int ck = 0; ck < nCk; ck++) {
        if (ck == nCk - 1) { CPA_WAIT0; } else { CPA_WAIT1; }
        __syncthreads();
        const uint32_t tb = smb + (ck & 1) * TG_STAGE;

        #pragma unroll
        for (int kc = 0; kc < 4; kc++) {
            uint32_t af[2][4];
            #pragma unroll
            for (int mi = 0; mi < 2; mi++) {
                const uint32_t a = tb + sw128(wm + mi * 16 + fr, kc * 2 + fc);
                ldsm4(af[mi][0], af[mi][1], af[mi][2], af[mi][3], a);
            }
            #pragma unroll
            for (int ng = 0; ng < 4; ng++) {
                uint32_t bh4[4];
                const uint32_t ba = tb + 16384 + sw128(wn + ng * 16 + fr, kc * 2 + fc);
                ldsm4(bh4[0], bh4[1], bh4[2], bh4[3], ba);
                #pragma unroll
                for (int mi = 0; mi < 2; mi++)
                    #pragma unroll
                    for (int oo = 0; oo < 2; oo++) {
                        uint32_t bhf[2] = { bh4[oo], bh4[oo + 2] };
                        mma_f16(acc[mi][ng * 2 + oo], af[mi], bhf);
                    }
            }
        }
        __syncthreads();
        if (ck + 2 < nCk) stage(ck + 2, ck & 1);
        CPA_COMMIT;
    }

    if (mode == 0) {
        #pragma unroll
        for (int mi = 0; mi < 2; mi++)
            #pragma unroll
            for (int nj = 0; nj < 8; nj++) {
                const float* c = acc[mi][nj];
                const int row = brow + wm + mi * 16 + (lane >> 2);
                const int col = bcol + wn + (nj >> 1) * 16 + (nj & 1) * 8 + (lane & 3) * 2;
                *(float2*)(C + (size_t)row * N + col)       = make_float2(c[0], c[1]);
                *(float2*)(C + (size_t)(row + 8) * N + col) = make_float2(c[2], c[3]);
            }
        return;
    }

    const int q = lane & 3, g = lane >> 2;
    const int headbase = bcol + wn;
    const bool vpath = (mode == 2) && (headbase >= 1024);

    #pragma unroll
    for (int mi = 0; mi < 2; mi++) {
        #pragma unroll
        for (int half = 0; half < 2; half++) {
            const int row = brow + wm + mi * 16 + g + half * 8;

            if (vpath) {
                const size_t ob = (size_t)row * 1024 + (headbase - 1024);
                #pragma unroll
                for (int nj = 0; nj < 8; nj++) {
                    const int cn = (nj >> 1) * 16 + (nj & 1) * 8 + q * 2;
                    *(uint32_t*)(o2 + ob + cn) =
                        hpack(acc[mi][nj][half * 2], acc[mi][nj][half * 2 + 1]);
                }
                continue;
            }

            float ss = 0.0f;
            #pragma unroll
            for (int nj = 0; nj < 8; nj++) {
                const float a0 = acc[mi][nj][half * 2];
                const float a1 = acc[mi][nj][half * 2 + 1];
                ss += a0 * a0 + a1 * a1;
            }
            ss += __shfl_xor_sync(0xffffffffu, ss, 1);
            ss += __shfl_xor_sync(0xffffffffu, ss, 2);
            const float inv = rsqrtf(ss * (1.0f / 64.0f) + 1.1920929e-07f);
            const float fpos = (float)pos[row];
            const float scale = (mode == 1) ? 0.125f : 1.0f;
            const size_t ob = (size_t)row * 1024 + headbase;

            #pragma unroll
            for (int p = 0; p < 4; p++) {
                const int c0 = (p >> 1) * 16 + (p & 1) * 8 + q * 2;
                float oA[2], oB[2];
                #pragma unroll
                for (int e = 0; e < 2; e++) {
                    const int c = c0 + e;
                    const float y1 = acc[mi][p][half * 2 + e]     * inv * nw[c]      * scale;
                    const float y2 = acc[mi][p + 4][half * 2 + e] * inv * nw[c + 32] * scale;
                    float sn, cs;
                    sincosf(fpos * INVF[c], &sn, &cs);
                    oA[e] = y1 * cs - y2 * sn;
                    oB[e] = y2 * cs + y1 * sn;
                }
                *(uint32_t*)(o1 + ob + c0)      = hpack(oA[0], oA[1]);
                *(uint32_t*)(o1 + ob + c0 + 32) = hpack(oB[0], oB[1]);
            }
        }
    }
}

// ---------------------------------------------------------------------------
// attention core — round-14 version (fixed-max softmax, 2-stage KV).
// smem: Q 16K @0 | stage0 {K 8K, V 8K} @16384 | stage1 @32768  (48KB used)
// ---------------------------------------------------------------------------
__device__ __forceinline__ void attn_core(
    int qx, int bh,
    const U16* __restrict__ q16_, const U16* __restrict__ k16_,
    const U16* __restrict__ v16_, U16* __restrict__ x16_, U16* sma)
{
    const uint32_t smb = (uint32_t)__cvta_generic_to_shared(sma);
    const int tid = threadIdx.x, warp = tid >> 5, lane = tid & 31;
    const int b = bh >> 4, h = bh & 15;
    const int row0 = qx * 128;
    const int wm = warp * 16;
    const int fr = ((lane >> 3) & 1) * 8 + (lane & 7);
    const int fc = lane >> 4;

    const size_t bn0 = (size_t)b * NSEQ + row0;
    const size_t bm0 = (size_t)b * MSEQ;

    #pragma unroll
    for (int i = 0; i < 4; i++) {
        const int c = tid + i * 256;
        const int r = c >> 3, ch = c & 7;
        const size_t g = (bn0 + r) * 1024 + h * HD + ch * 8;
        cpa16(smb + sw128(r, ch), q16_ + g);
    }
    CPA_COMMIT;

    auto stageKV = [&](int kt, int s) {
        const uint32_t base = smb + 16384 + s * 16384;
        #pragma unroll
        for (int i = 0; i < 2; i++) {
            const int c = tid + i * 256;
            const int r = c >> 3, ch = c & 7;
            const size_t g = (bm0 + kt * 64 + r) * 1024 + h * HD + ch * 8;
            const uint32_t so = sw128(r, ch);
            cpa16(base + so,        k16_ + g);
            cpa16(base + 8192 + so, v16_ + g);
        }
    };
    stageKV(0, 0); CPA_COMMIT;
    stageKV(1, 1); CPA_COMMIT;

    CPA_WAIT2;
    __syncthreads();
    uint32_t qf[4][4];
    #pragma unroll
    for (int kc = 0; kc < 4; kc++)
        ldsm4(qf[kc][0], qf[kc][1], qf[kc][2], qf[kc][3],
              smb + sw128(wm + fr, kc * 2 + fc));

    float li0 = 0.0f, li1 = 0.0f;
    float acc[8][4];
    #pragma unroll
    for (int na = 0; na < 8; na++)
        #pragma unroll
        for (int c = 0; c < 4; c++) acc[na][c] = 0.0f;

    const int nT = MSEQ / 64;
    for (int kt = 0; kt < nT; kt++) {
        if (kt == nT - 1) { CPA_WAIT0; } else { CPA_WAIT1; }
        __syncthreads();
        const uint32_t kb = smb + 16384 + (kt & 1) * 16384;

        float s[8][4];
        #pragma unroll
        for (int na = 0; na < 8; na++)
            #pragma unroll
            for (int c = 0; c < 4; c++) s[na][c] = 0.0f;

        #pragma unroll
        for (int kc = 0; kc < 4; kc++) {
            #pragma unroll
            for (int jg = 0; jg < 4; jg++) {
                uint32_t kr[4];
                ldsm4(kr[0], kr[1], kr[2], kr[3],
                      kb + sw128(jg * 16 + fr, kc * 2 + fc));
                #pragma unroll
                for (int oo = 0; oo < 2; oo++) {
                    uint32_t bh2[2] = { kr[oo], kr[oo + 2] };
                    mma_f16(s[jg * 2 + oo], qf[kc], bh2);
                }
            }
        }

        #pragma unroll
        for (int na = 0; na < 8; na++) {
            s[na][0] = __expf(s[na][0] - 8.0f);
            s[na][1] = __expf(s[na][1] - 8.0f);
            s[na][2] = __expf(s[na][2] - 8.0f);
            s[na][3] = __expf(s[na][3] - 8.0f);
            li0 += s[na][0] + s[na][1];
            li1 += s[na][2] + s[na][3];
        }

        #pragma unroll
        for (int jc = 0; jc < 4; jc++) {
            uint32_t ph[4];
            ph[0] = hpack(s[2 * jc][0],     s[2 * jc][1]);
            ph[1] = hpack(s[2 * jc][2],     s[2 * jc][3]);
            ph[2] = hpack(s[2 * jc + 1][0], s[2 * jc + 1][1]);
            ph[3] = hpack(s[2 * jc + 1][2], s[2 * jc + 1][3]);
            #pragma unroll
            for (int dg = 0; dg < 4; dg++) {
                uint32_t vr[4];
                ldsm4t(vr[0], vr[1], vr[2], vr[3],
                       kb + 8192 + sw128(jc * 16 + fr, dg * 2 + fc));
                #pragma unroll
                for (int oo = 0; oo < 2; oo++) {
                    uint32_t bh2[2] = { vr[oo * 2], vr[oo * 2 + 1] };
                    mma_f16(acc[dg * 2 + oo], ph, bh2);
                }
            }
        }

        __syncthreads();
        if (kt + 2 < nT) stageKV(kt + 2, kt & 1);
        CPA_COMMIT;
    }

    li0 += __shfl_xor_sync(0xffffffffu, li0, 1);
    li0 += __shfl_xor_sync(0xffffffffu, li0, 2);
    li1 += __shfl_xor_sync(0xffffffffu, li1, 1);
    li1 += __shfl_xor_sync(0xffffffffu, li1, 2);
    const float inv0 = 1.0f / li0;
    const float inv1 = 1.0f / li1;
    const size_t r0 = bn0 + wm + (lane >> 2);
    const size_t e0 = r0 * 1024 + h * HD + (lane & 3) * 2;
    const size_t e1 = (r0 + 8) * 1024 + h * HD + (lane & 3) * 2;
    #pragma unroll
    for (int na = 0; na < 8; na++) {
        *(uint32_t*)(x16_ + e0 + na * 8) = hpack(acc[na][0] * inv0, acc[na][1] * inv0);
        *(uint32_t*)(x16_ + e1 + na * 8) = hpack(acc[na][2] * inv1, acc[na][3] * inv1);
    }
}

// ---------------------------------------------------------------------------
// fused kernel: [0,1536) qkv | [1536,2560) attention | [2560,3072) out GEMM.
// Dependencies via counters; block-id order respects the DAG.
// ---------------------------------------------------------------------------
__global__ __launch_bounds__(256, 2) void fused_kernel(
    const U16* __restrict__ tgt16, const U16* __restrict__ src16,
    const U16* __restrict__ wq16, const U16* __restrict__ wkv16,
    const U16* __restrict__ wo16,
    const int* __restrict__ tgt_pos, const int* __restrict__ src_pos,
    const float* __restrict__ qw, const float* __restrict__ kw,
    U16* __restrict__ q16, U16* __restrict__ k16, U16* __restrict__ v16,
    U16* __restrict__ x16, float* __restrict__ out)
{
    extern __shared__ U16 smg[];
    const int id = blockIdx.x;

    if (id < 1536) {
        const int by = id / 24, bx = id % 24;
        if (bx < 8) {
            gemm_core(1, tgt16, wq16, nullptr, tgt_pos, qw, q16, nullptr,
                      1024, 1024, by * 128, bx * 128, smg);
            signal_cnt(&g_qcnt[by]);
        } else {
            gemm_core(2, src16, wkv16, nullptr, src_pos, kw, k16, v16,
                      2048, 1024, by * 128, (bx - 8) * 128, smg);
            signal_cnt(&g_kvcnt[by >> 4]);
        }
    } else if (id < 2560) {
        const int a = id - 1536;
        const int qx = a & 15, bh = a >> 4;
        const int b = bh >> 4;
        wait_cnt(&g_kvcnt[b], 256);
        wait_cnt(&g_qcnt[b * 16 + qx], 8);
        attn_core(qx, bh, q16, k16, v16, x16, smg);
        signal_cnt(&g_xcnt[b * 16 + qx]);
    } else {
        const int g = id - 2560;
        const int cb = g & 7, rb = g >> 3;
        wait_cnt(&g_xcnt[rb], 16);
        gemm_core(0, x16, wo16, out, nullptr, nullptr, nullptr, nullptr,
                  1024, 1024, rb * 128, cb * 128, smg);
    }
}

// ---------------------------------------------------------------------------
extern "C" void kernel_launch(void* const* d_in, const int* in_sizes, int n_in,
                              void* d_out, int out_size)
{
    const float* tgt     = (const float*)d_in[0];
    const float* src     = (const float*)d_in[1];
    const int*   tgt_pos = (const int*)  d_in[2];
    const int*   src_pos = (const int*)  d_in[3];
    const float* Wq      = (const float*)d_in[4];
    const float* Wkv     = (const float*)d_in[5];
    const float* Wo      = (const float*)d_in[6];
    const float* qw      = (const float*)d_in[7];
    const float* kw      = (const float*)d_in[8];
    float* out = (float*)d_out;

    U16 *tgt16, *src16, *x16, *wq16, *wkv16, *wo16;
    U16 *q16, *k16, *v16;
    cudaGetSymbolAddress((void**)&tgt16, s_tgt16);
    cudaGetSymbolAddress((void**)&src16, s_src16);
    cudaGetSymbolAddress((void**)&x16,   s_x16);
    cudaGetSymbolAddress((void**)&wq16,  s_wq16);
    cudaGetSymbolAddress((void**)&wkv16, s_wkv16);
    cudaGetSymbolAddress((void**)&wo16,  s_wo16);
    cudaGetSymbolAddress((void**)&q16,   s_q16);
    cudaGetSymbolAddress((void**)&k16,   s_k16);
    cudaGetSymbolAddress((void**)&v16,   s_v16);

    cudaFuncSetAttribute(fused_kernel,
                         cudaFuncAttributeMaxDynamicSharedMemorySize, FUSED_SMEM);

    // conversions + counter reset
    megaconv_kernel<<<20480, 256>>>(tgt, src, Wq, Wkv, Wo,
                                    tgt16, src16, wq16, wkv16, wo16);

    // entire attention block in one launch with intra-grid dependencies
    fused_kernel<<<3072, 256, FUSED_SMEM>>>(
        tgt16, src16, wq16, wkv16, wo16, tgt_pos, src_pos, qw, kw,
        q16, k16, v16, x16, out);
}